// round 6
// baseline (speedup 1.0000x reference)
#include <cuda_runtime.h>
#include <cstdint>

// ============================================================================
// LoRALinear: out = x @ W^T + b + 2 * x @ (A @ B^T)^T
//   x:(2,4096,4096) f32, W:(4096,4096), b:(4096), A:(4096,8), B:(4096,8)
//
// Base-ISA tensor-core path (harness targets sm_100, no tcgen05):
//   mma.sync.aligned.m16n8k8.row.col.f32.tf32.tf32.f32  + cp.async pipeline.
//
// R5 -> R6: HMMA tf32 rt_SMSP≈8 puts the chip floor at ~1000us; the 1385us
// GEMM was ~30% above it from correlated per-CTA barriers (1 CTA/SM).
// This round: 128x128 CTA tile, 3 stages (96KB smem) -> 2 CTAs/SM so each
// SMSP interleaves two independent k-phases. Warp tile 32x64 (64 acc regs),
// __launch_bounds__(256,2).
// ============================================================================

#define BM 128
#define BN 128
#define BK 32
#define STAGES 3
#define KDIM 4096
#define NDIM 4096
#define MDIM 8192
#define KTILES (KDIM / BK)   // 128

#define A_TILE_FLOATS (BM * BK)              // 4096
#define B_TILE_FLOATS (BN * BK)              // 4096
#define STAGE_FLOATS  (A_TILE_FLOATS + B_TILE_FLOATS)   // 8192
#define SMEM_BYTES    (STAGES * STAGE_FLOATS * 4)       // 98304

// Scratch (device-global; runtime allocation is prohibited)
__device__ float g_Wp[(size_t)NDIM * KDIM];        // 64 MB
__device__ float g_xr[(size_t)MDIM * KDIM];        // 128 MB

// ---------------------------------------------------------------------------
// helpers
// ---------------------------------------------------------------------------
__device__ __forceinline__ uint32_t smem_u32(const void* p) {
    uint32_t a;
    asm("{ .reg .u64 t; cvta.to.shared.u64 t, %1; cvt.u32.u64 %0, t; }"
        : "=r"(a) : "l"(p));
    return a;
}

__device__ __forceinline__ void cp_async16(uint32_t dst, const void* src) {
    asm volatile("cp.async.cg.shared.global [%0], [%1], 16;"
                 :: "r"(dst), "l"(src) : "memory");
}
#define CP_COMMIT() asm volatile("cp.async.commit_group;" ::: "memory")
#define CP_WAIT(n)  asm volatile("cp.async.wait_group %0;" :: "n"(n) : "memory")

// tf32 destination is a b32 register per PTX ISA ("=r", NOT "=f")
__device__ __forceinline__ float rna_tf32(float v) {
    uint32_t r;
    asm("cvt.rna.tf32.f32 %0, %1;" : "=r"(r) : "f"(v));
    return __uint_as_float(r);
}

// m16n8k8 tf32 MMA, D += A*B (accumulate in place)
__device__ __forceinline__ void mma_tf32(float* d, const uint32_t* a,
                                         const uint32_t* b) {
    asm volatile(
        "mma.sync.aligned.m16n8k8.row.col.f32.tf32.tf32.f32 "
        "{%0,%1,%2,%3}, {%4,%5,%6,%7}, {%8,%9}, {%0,%1,%2,%3};"
        : "+f"(d[0]), "+f"(d[1]), "+f"(d[2]), "+f"(d[3])
        : "r"(a[0]), "r"(a[1]), "r"(a[2]), "r"(a[3]), "r"(b[0]), "r"(b[1]));
}

// swizzled float index within a (rows x 32) tile: XOR 16B-chunk by row&7
__device__ __forceinline__ int swz_idx(int row, int col) {
    return row * BK + ((((col >> 2) ^ row) & 7) << 2) + (col & 3);
}

// ---------------------------------------------------------------------------
// Kernel 1: W' = rna_tf32(W + 2 * A @ B^T)   (W:(N,K) row-major)
// ---------------------------------------------------------------------------
__global__ void prep_w_kernel(const float* __restrict__ W,
                              const float* __restrict__ A,
                              const float* __restrict__ Bm) {
    __shared__ float sA[16 * 8];
    __shared__ float sB[1024 * 9];

    const int t = threadIdx.x;
    const int bo = blockIdx.x;       // 16 rows per block

    if (t < 128) sA[t] = A[(bo * 16 + (t >> 3)) * 8 + (t & 7)];

    for (int c = 0; c < 4; c++) {
        const int i0 = c * 1024;
        __syncthreads();
        for (int j = 0; j < 32; j++) {
            int li = t + j * 256;
            sB[(li >> 3) * 9 + (li & 7)] = Bm[i0 * 8 + li];
        }
        __syncthreads();
        for (int ol = 0; ol < 16; ol++) {
            const int o = bo * 16 + ol;
            float a0 = sA[ol * 8 + 0], a1 = sA[ol * 8 + 1];
            float a2 = sA[ol * 8 + 2], a3 = sA[ol * 8 + 3];
            float a4 = sA[ol * 8 + 4], a5 = sA[ol * 8 + 5];
            float a6 = sA[ol * 8 + 6], a7 = sA[ol * 8 + 7];
            for (int j = 0; j < 4; j++) {
                int il = t + j * 256;
                const float* br = &sB[il * 9];
                float d = a0 * br[0] + a1 * br[1] + a2 * br[2] + a3 * br[3]
                        + a4 * br[4] + a5 * br[5] + a6 * br[6] + a7 * br[7];
                int idx = o * KDIM + i0 + il;
                g_Wp[idx] = rna_tf32(W[idx] + 2.0f * d);
            }
        }
    }
}

// ---------------------------------------------------------------------------
// Kernel 2: xr = rna_tf32(x)
// ---------------------------------------------------------------------------
__global__ void round_x_kernel(const float4* __restrict__ x, int n4) {
    float4* xr = reinterpret_cast<float4*>(g_xr);
    for (int i = blockIdx.x * blockDim.x + threadIdx.x; i < n4;
         i += gridDim.x * blockDim.x) {
        float4 v = x[i];
        v.x = rna_tf32(v.x); v.y = rna_tf32(v.y);
        v.z = rna_tf32(v.z); v.w = rna_tf32(v.w);
        xr[i] = v;
    }
}

// ---------------------------------------------------------------------------
// Kernel 3: out = xr @ W'^T + bias   (mma.sync tf32, 128x128 tile, 3-stage,
//                                     2 CTAs/SM)
// ---------------------------------------------------------------------------
__global__ __launch_bounds__(256, 2)
void lora_gemm_tf32(const float* __restrict__ bias, float* __restrict__ out) {
    extern __shared__ float smem[];
    __shared__ float sbias[BN];

    const uint32_t sbase = smem_u32(smem);
    const int tid = threadIdx.x;
    const int wid = tid >> 5;
    const int lane = tid & 31;
    const int ntile = blockIdx.x;   // 0..31  (fastest -> W' stays L2-resident)
    const int mtile = blockIdx.y;   // 0..63

    // warp tile: 32x64.  4 m-positions x 2 n-positions
    const int mrow_s = (wid & 3) * 32;
    const int ncol_s = (wid >> 2) * 64;
    const int r0 = lane >> 2;       // 0..7
    const int c0 = lane & 3;        // 0..3

    if (tid < BN) sbias[tid] = bias[ntile * BN + tid];

    // hoisted per-thread producer offsets
    const int prow = tid >> 3;           // 0..31
    const int pch  = tid & 7;            // 0..7
    const float* Abase = g_xr + (size_t)(mtile * BM + prow) * KDIM + pch * 4;
    const float* Bbase = g_Wp + (size_t)(ntile * BN + prow) * KDIM + pch * 4;
    uint32_t aswz[4], bswz[4];
    #pragma unroll
    for (int i = 0; i < 4; i++) {
        aswz[i] = (uint32_t)swz_idx(prow + i * 32, pch * 4) * 4u;
        bswz[i] = aswz[i];               // same (row, chunk) pattern
    }

    // ---- producer: load k-tile kt into stage s ----
    auto load_tile = [&](int kt, int s) {
        const uint32_t abytes = sbase + (uint32_t)(s * STAGE_FLOATS) * 4u;
        const uint32_t bbytes = abytes + A_TILE_FLOATS * 4u;
        const int kbase = kt * BK;
        #pragma unroll
        for (int i = 0; i < 4; i++)            // A: 128 rows x 8 chunks
            cp_async16(abytes + aswz[i], Abase + (size_t)(i * 32) * KDIM + kbase);
        #pragma unroll
        for (int i = 0; i < 4; i++)            // B: 128 rows x 8 chunks
            cp_async16(bbytes + bswz[i], Bbase + (size_t)(i * 32) * KDIM + kbase);
        CP_COMMIT();
    };

    // prologue: 2 stages in flight
    load_tile(0, 0);
    load_tile(1, 1);

    float acc[2][8][4];
    #pragma unroll
    for (int mt = 0; mt < 2; mt++)
        #pragma unroll
        for (int nt = 0; nt < 8; nt++)
            #pragma unroll
            for (int q = 0; q < 4; q++) acc[mt][nt][q] = 0.0f;

    int s = 0;
    for (int kt = 0; kt < KTILES; kt++) {
        if (kt < KTILES - 1) CP_WAIT(1);
        else                 CP_WAIT(0);
        __syncthreads();

        const int nk = kt + STAGES - 1;
        if (nk < KTILES) {
            int ns = s + 2; if (ns >= STAGES) ns -= STAGES;
            load_tile(nk, ns);
        }

        const uint32_t* As =
            reinterpret_cast<const uint32_t*>(smem + s * STAGE_FLOATS);
        const uint32_t* Bs = As + A_TILE_FLOATS;

        #pragma unroll
        for (int kk = 0; kk < 4; kk++) {
            const int ca = kk * 8 + c0;
            uint32_t a[2][4], bfr[8][2];
            #pragma unroll
            for (int mt = 0; mt < 2; mt++) {
                const int rA = mrow_s + mt * 16 + r0;
                a[mt][0] = As[swz_idx(rA,     ca)];
                a[mt][1] = As[swz_idx(rA + 8, ca)];
                a[mt][2] = As[swz_idx(rA,     ca + 4)];
                a[mt][3] = As[swz_idx(rA + 8, ca + 4)];
            }
            #pragma unroll
            for (int nt = 0; nt < 8; nt++) {
                const int rB = ncol_s + nt * 8 + r0;
                bfr[nt][0] = Bs[swz_idx(rB, ca)];
                bfr[nt][1] = Bs[swz_idx(rB, ca + 4)];
            }
            #pragma unroll
            for (int mt = 0; mt < 2; mt++)
                #pragma unroll
                for (int nt = 0; nt < 8; nt++)
                    mma_tf32(acc[mt][nt], a[mt], bfr[nt]);
        }

        if (++s == STAGES) s = 0;
    }

    // ---- epilogue: float2 stores with bias ----
    #pragma unroll
    for (int mt = 0; mt < 2; mt++) {
        const int m = mtile * BM + mrow_s + mt * 16 + r0;
        #pragma unroll
        for (int nt = 0; nt < 8; nt++) {
            const int nloc = ncol_s + nt * 8 + 2 * c0;
            const int n = ntile * BN + nloc;
            const float b0 = sbias[nloc], b1 = sbias[nloc + 1];
            float2 v0 = make_float2(acc[mt][nt][0] + b0, acc[mt][nt][1] + b1);
            float2 v1 = make_float2(acc[mt][nt][2] + b0, acc[mt][nt][3] + b1);
            *reinterpret_cast<float2*>(out + (size_t)m * NDIM + n) = v0;
            *reinterpret_cast<float2*>(out + (size_t)(m + 8) * NDIM + n) = v1;
        }
    }
}

// ---------------------------------------------------------------------------
extern "C" void kernel_launch(void* const* d_in, const int* in_sizes, int n_in,
                              void* d_out, int out_size) {
    const float* x = (const float*)d_in[0];   // (2,4096,4096)
    const float* W = (const float*)d_in[1];   // (4096,4096)
    const float* b = (const float*)d_in[2];   // (4096)
    const float* A = (const float*)d_in[3];   // (4096,8)
    const float* B = (const float*)d_in[4];   // (4096,8)
    float* out = (float*)d_out;

    cudaFuncSetAttribute(lora_gemm_tf32,
                         cudaFuncAttributeMaxDynamicSharedMemorySize, SMEM_BYTES);

    prep_w_kernel<<<256, 256>>>(W, A, B);
    round_x_kernel<<<2048, 256>>>(reinterpret_cast<const float4*>(x),
                                  (int)((size_t)MDIM * KDIM / 4));
    lora_gemm_tf32<<<dim3(NDIM / BN, MDIM / BM), 256, SMEM_BYTES>>>(b, out);
}

// round 10
// speedup vs baseline: 1.9074x; 1.9074x over previous
#include <cuda_runtime.h>
#include <cuda_fp16.h>
#include <cstdint>

// ============================================================================
// LoRALinear: out = x @ W^T + b + 2 * x @ (A @ B^T)^T
//   x:(2,4096,4096) f32, W:(4096,4096), b:(4096), A:(4096,8), B:(4096,8)
//
// fp16 m16n8k16 path (same 10-bit mantissa as tf32, 2x MACs per HMMA).
// CTA 128x256, BK=64 halves (=128B rows), 4-stage cp.async, 8 warps x 64x64,
// fp32 accumulators, 1 CTA/SM.
// R8/R9: container infra flakes (never reached compile); resubmitting.
// ============================================================================

#define BM 128
#define BN 256
#define BKH 64                 // k-tile in halves (128 bytes per row)
#define STAGES 4
#define KDIM 4096
#define NDIM 4096
#define MDIM 8192
#define KTILES (KDIM / BKH)    // 64

// per-stage b32 words: A = 128 rows x 32, B = 256 rows x 32
#define A_TILE_W (BM * 32)                   // 4096
#define B_TILE_W (BN * 32)                   // 8192
#define STAGE_W  (A_TILE_W + B_TILE_W)       // 12288 (48KB)
#define SMEM_BYTES (STAGES * STAGE_W * 4)    // 196608

// Scratch (device-global; runtime allocation prohibited)
__device__ __half g_Wh[(size_t)NDIM * KDIM];   // 32 MB
__device__ __half g_xh[(size_t)MDIM * KDIM];   // 64 MB

// ---------------------------------------------------------------------------
// helpers
// ---------------------------------------------------------------------------
__device__ __forceinline__ uint32_t smem_u32(const void* p) {
    uint32_t a;
    asm("{ .reg .u64 t; cvta.to.shared.u64 t, %1; cvt.u32.u64 %0, t; }"
        : "=r"(a) : "l"(p));
    return a;
}

__device__ __forceinline__ void cp_async16(uint32_t dst, const void* src) {
    asm volatile("cp.async.cg.shared.global [%0], [%1], 16;"
                 :: "r"(dst), "l"(src) : "memory");
}
#define CP_COMMIT() asm volatile("cp.async.commit_group;" ::: "memory")
#define CP_WAIT(n)  asm volatile("cp.async.wait_group %0;" :: "n"(n) : "memory")

__device__ __forceinline__ uint32_t h2_bits(__half2 h) {
    union { __half2 h; uint32_t u; } cvt;
    cvt.h = h;
    return cvt.u;
}

// m16n8k16 f16 MMA, fp32 accum, D += A*B
__device__ __forceinline__ void mma_f16(float* d, const uint32_t* a,
                                        const uint32_t* b) {
    asm volatile(
        "mma.sync.aligned.m16n8k16.row.col.f32.f16.f16.f32 "
        "{%0,%1,%2,%3}, {%4,%5,%6,%7}, {%8,%9}, {%0,%1,%2,%3};"
        : "+f"(d[0]), "+f"(d[1]), "+f"(d[2]), "+f"(d[3])
        : "r"(a[0]), "r"(a[1]), "r"(a[2]), "r"(a[3]), "r"(b[0]), "r"(b[1]));
}

// swizzled b32 index within a (rows x 32 b32) tile: XOR 16B-chunk by row&7
__device__ __forceinline__ int swz_idx(int row, int col) {
    return row * 32 + ((((col >> 2) ^ row) & 7) << 2) + (col & 3);
}

// ---------------------------------------------------------------------------
// Kernel 1: W' = fp16_rn(W + 2 * A @ B^T)   (W:(N,K) row-major)
// ---------------------------------------------------------------------------
__global__ void prep_w_kernel(const float* __restrict__ W,
                              const float* __restrict__ A,
                              const float* __restrict__ Bm) {
    __shared__ float sA[16 * 8];
    __shared__ float sB[1024 * 9];

    const int t = threadIdx.x;
    const int bo = blockIdx.x;       // 16 rows per block

    if (t < 128) sA[t] = A[(bo * 16 + (t >> 3)) * 8 + (t & 7)];

    for (int c = 0; c < 4; c++) {
        const int i0 = c * 1024;
        __syncthreads();
        for (int j = 0; j < 32; j++) {
            int li = t + j * 256;
            sB[(li >> 3) * 9 + (li & 7)] = Bm[i0 * 8 + li];
        }
        __syncthreads();
        for (int ol = 0; ol < 16; ol++) {
            const int o = bo * 16 + ol;
            float a0 = sA[ol * 8 + 0], a1 = sA[ol * 8 + 1];
            float a2 = sA[ol * 8 + 2], a3 = sA[ol * 8 + 3];
            float a4 = sA[ol * 8 + 4], a5 = sA[ol * 8 + 5];
            float a6 = sA[ol * 8 + 6], a7 = sA[ol * 8 + 7];
            for (int j = 0; j < 4; j++) {
                int il = t + j * 256;
                const float* br = &sB[il * 9];
                float d = a0 * br[0] + a1 * br[1] + a2 * br[2] + a3 * br[3]
                        + a4 * br[4] + a5 * br[5] + a6 * br[6] + a7 * br[7];
                int idx = o * KDIM + i0 + il;
                g_Wh[idx] = __float2half_rn(W[idx] + 2.0f * d);
            }
        }
    }
}

// ---------------------------------------------------------------------------
// Kernel 2: xh = fp16_rn(x)   (8 floats -> 8 halves = one uint4 store)
// ---------------------------------------------------------------------------
__global__ void conv_x_kernel(const float4* __restrict__ x, int n8) {
    uint4* xh = reinterpret_cast<uint4*>(g_xh);
    for (int i = blockIdx.x * blockDim.x + threadIdx.x; i < n8;
         i += gridDim.x * blockDim.x) {
        float4 f0 = x[2 * i];
        float4 f1 = x[2 * i + 1];
        uint4 v;
        v.x = h2_bits(__floats2half2_rn(f0.x, f0.y));
        v.y = h2_bits(__floats2half2_rn(f0.z, f0.w));
        v.z = h2_bits(__floats2half2_rn(f1.x, f1.y));
        v.w = h2_bits(__floats2half2_rn(f1.z, f1.w));
        xh[i] = v;
    }
}

// ---------------------------------------------------------------------------
// Kernel 3: out = xh @ Wh^T + bias  (mma.sync f16 k16, 128x256, 4-stage)
// ---------------------------------------------------------------------------
__global__ __launch_bounds__(256, 1)
void lora_gemm_f16(const float* __restrict__ bias, float* __restrict__ out) {
    extern __shared__ float smem[];
    __shared__ float sbias[BN];

    const uint32_t sbase = smem_u32(smem);
    const int tid = threadIdx.x;
    const int wid = tid >> 5;
    const int lane = tid & 31;
    const int ntile = blockIdx.x;   // 0..15 (fastest: W' L2-resident)
    const int mtile = blockIdx.y;   // 0..63

    // warp tile 64x64: warp_m {0,1}, warp_n {0..3}
    const int mrow_s = (wid & 1) * 64;
    const int ncol_s = (wid >> 1) * 64;
    const int r0 = lane >> 2;       // 0..7
    const int c0 = lane & 3;        // 0..3

    sbias[tid] = bias[ntile * BN + tid];

    // producer offsets: each thread owns (row=tid>>3, chunk=tid&7), 16B chunks
    const int prow = tid >> 3;           // 0..31
    const int pch  = tid & 7;            // 0..7
    const __half* Abase = g_xh + (size_t)(mtile * BM + prow) * KDIM + pch * 8;
    const __half* Bbase = g_Wh + (size_t)(ntile * BN + prow) * KDIM + pch * 8;
    uint32_t aswz[4], bswz[8];
    #pragma unroll
    for (int i = 0; i < 4; i++) aswz[i] = (uint32_t)swz_idx(prow + i * 32, pch * 4) * 4u;
    #pragma unroll
    for (int i = 0; i < 8; i++) bswz[i] = (uint32_t)swz_idx(prow + i * 32, pch * 4) * 4u;

    auto load_tile = [&](int kt, int s) {
        const uint32_t abytes = sbase + (uint32_t)(s * STAGE_W) * 4u;
        const uint32_t bbytes = abytes + A_TILE_W * 4u;
        const int kbase = kt * BKH;   // halves
        #pragma unroll
        for (int i = 0; i < 4; i++)            // A: 128 rows
            cp_async16(abytes + aswz[i], Abase + (size_t)(i * 32) * KDIM + kbase);
        #pragma unroll
        for (int i = 0; i < 8; i++)            // B: 256 rows
            cp_async16(bbytes + bswz[i], Bbase + (size_t)(i * 32) * KDIM + kbase);
        CP_COMMIT();
    };

    #pragma unroll
    for (int s = 0; s < STAGES - 1; s++) load_tile(s, s);

    float acc[4][8][4];
    #pragma unroll
    for (int mt = 0; mt < 4; mt++)
        #pragma unroll
        for (int nt = 0; nt < 8; nt++)
            #pragma unroll
            for (int q = 0; q < 4; q++) acc[mt][nt][q] = 0.0f;

    for (int kt = 0; kt < KTILES; kt++) {
        const int s = kt & (STAGES - 1);
        if (kt <= KTILES - 3)       CP_WAIT(2);
        else if (kt == KTILES - 2)  CP_WAIT(1);
        else                        CP_WAIT(0);
        __syncthreads();

        const int nk = kt + STAGES - 1;
        if (nk < KTILES) load_tile(nk, nk & (STAGES - 1));

        const uint32_t* As =
            reinterpret_cast<const uint32_t*>(smem + s * STAGE_W);
        const uint32_t* Bs = As + A_TILE_W;

        #pragma unroll
        for (int ks = 0; ks < 4; ks++) {       // 4 x k16 = BKH=64 halves
            const int ca = ks * 8 + c0;        // b32 column
            uint32_t a[4][4], bfr[8][2];
            #pragma unroll
            for (int mt = 0; mt < 4; mt++) {
                const int rA = mrow_s + mt * 16 + r0;
                a[mt][0] = As[swz_idx(rA,     ca)];
                a[mt][1] = As[swz_idx(rA + 8, ca)];
                a[mt][2] = As[swz_idx(rA,     ca + 4)];
                a[mt][3] = As[swz_idx(rA + 8, ca + 4)];
            }
            #pragma unroll
            for (int nt = 0; nt < 8; nt++) {
                const int rB = ncol_s + nt * 8 + r0;
                bfr[nt][0] = Bs[swz_idx(rB, ca)];
                bfr[nt][1] = Bs[swz_idx(rB, ca + 4)];
            }
            #pragma unroll
            for (int mt = 0; mt < 4; mt++)
                #pragma unroll
                for (int nt = 0; nt < 8; nt++)
                    mma_f16(acc[mt][nt], a[mt], bfr[nt]);
        }
    }

    // ---- epilogue: float2 stores with bias ----
    #pragma unroll
    for (int mt = 0; mt < 4; mt++) {
        const int m = mtile * BM + mrow_s + mt * 16 + r0;
        #pragma unroll
        for (int nt = 0; nt < 8; nt++) {
            const int nloc = ncol_s + nt * 8 + 2 * c0;
            const int n = ntile * BN + nloc;
            const float b0 = sbias[nloc], b1 = sbias[nloc + 1];
            float2 v0 = make_float2(acc[mt][nt][0] + b0, acc[mt][nt][1] + b1);
            float2 v1 = make_float2(acc[mt][nt][2] + b0, acc[mt][nt][3] + b1);
            *reinterpret_cast<float2*>(out + (size_t)m * NDIM + n) = v0;
            *reinterpret_cast<float2*>(out + (size_t)(m + 8) * NDIM + n) = v1;
        }
    }
}

// ---------------------------------------------------------------------------
extern "C" void kernel_launch(void* const* d_in, const int* in_sizes, int n_in,
                              void* d_out, int out_size) {
    const float* x = (const float*)d_in[0];   // (2,4096,4096)
    const float* W = (const float*)d_in[1];   // (4096,4096)
    const float* b = (const float*)d_in[2];   // (4096)
    const float* A = (const float*)d_in[3];   // (4096,8)
    const float* B = (const float*)d_in[4];   // (4096,8)
    float* out = (float*)d_out;

    cudaFuncSetAttribute(lora_gemm_f16,
                         cudaFuncAttributeMaxDynamicSharedMemorySize, SMEM_BYTES);

    prep_w_kernel<<<256, 256>>>(W, A, B);
    conv_x_kernel<<<2048, 256>>>(reinterpret_cast<const float4*>(x),
                                 (int)((size_t)MDIM * KDIM / 8));
    lora_gemm_f16<<<dim3(NDIM / BN, MDIM / BM), 256, SMEM_BYTES>>>(b, out);
}

// round 12
// speedup vs baseline: 1.9741x; 1.0350x over previous
#include <cuda_runtime.h>
#include <cuda_fp16.h>
#include <cstdint>

// ============================================================================
// LoRALinear: out = x @ W^T + b + 2 * x @ (A @ B^T)^T
//   x:(2,4096,4096) f32, W:(4096,4096), b:(4096), A:(4096,8), B:(4096,8)
//
// fp16 m16n8k16 path. CTA 128x256, BK=64 halves, 4-stage cp.async,
// 8 warps x 64x64, fp32 accumulators, 1 CTA/SM.
// Fragment loads via ldmatrix.m8n8.x4 (128 LDS -> 32 LDSM per warp-ktile).
// R11: container infra flake (never reached compile); resubmitting.
// ============================================================================

#define BM 128
#define BN 256
#define BKH 64                 // k-tile in halves (128 bytes per row)
#define STAGES 4
#define KDIM 4096
#define NDIM 4096
#define MDIM 8192
#define KTILES (KDIM / BKH)    // 64

// per-stage b32 words: A = 128 rows x 32, B = 256 rows x 32
#define A_TILE_W (BM * 32)                   // 4096
#define B_TILE_W (BN * 32)                   // 8192
#define STAGE_W  (A_TILE_W + B_TILE_W)       // 12288 (48KB)
#define SMEM_BYTES (STAGES * STAGE_W * 4)    // 196608

// Scratch (device-global; runtime allocation prohibited)
__device__ __half g_Wh[(size_t)NDIM * KDIM];   // 32 MB
__device__ __half g_xh[(size_t)MDIM * KDIM];   // 64 MB

// ---------------------------------------------------------------------------
// helpers
// ---------------------------------------------------------------------------
__device__ __forceinline__ uint32_t smem_u32(const void* p) {
    uint32_t a;
    asm("{ .reg .u64 t; cvta.to.shared.u64 t, %1; cvt.u32.u64 %0, t; }"
        : "=r"(a) : "l"(p));
    return a;
}

__device__ __forceinline__ void cp_async16(uint32_t dst, const void* src) {
    asm volatile("cp.async.cg.shared.global [%0], [%1], 16;"
                 :: "r"(dst), "l"(src) : "memory");
}
#define CP_COMMIT() asm volatile("cp.async.commit_group;" ::: "memory")
#define CP_WAIT(n)  asm volatile("cp.async.wait_group %0;" :: "n"(n) : "memory")

__device__ __forceinline__ uint32_t h2_bits(__half2 h) {
    union { __half2 h; uint32_t u; } cvt;
    cvt.h = h;
    return cvt.u;
}

// m16n8k16 f16 MMA, fp32 accum, D += A*B
__device__ __forceinline__ void mma_f16(float* d, const uint32_t* a,
                                        const uint32_t* b) {
    asm volatile(
        "mma.sync.aligned.m16n8k16.row.col.f32.f16.f16.f32 "
        "{%0,%1,%2,%3}, {%4,%5,%6,%7}, {%8,%9}, {%0,%1,%2,%3};"
        : "+f"(d[0]), "+f"(d[1]), "+f"(d[2]), "+f"(d[3])
        : "r"(a[0]), "r"(a[1]), "r"(a[2]), "r"(a[3]), "r"(b[0]), "r"(b[1]));
}

// ldmatrix x4: lane l supplies the row address of matrix (l>>3)
__device__ __forceinline__ void ldsm_x4(uint32_t* r, uint32_t addr) {
    asm volatile(
        "ldmatrix.sync.aligned.m8n8.x4.shared.b16 {%0,%1,%2,%3}, [%4];"
        : "=r"(r[0]), "=r"(r[1]), "=r"(r[2]), "=r"(r[3]) : "r"(addr));
}

// swizzled b32 index within a (rows x 32 b32) tile: XOR 16B-chunk by row&7
__device__ __forceinline__ int swz_idx(int row, int col) {
    return row * 32 + ((((col >> 2) ^ row) & 7) << 2) + (col & 3);
}

// ---------------------------------------------------------------------------
// Kernel 1: W' = fp16_rn(W + 2 * A @ B^T)   (W:(N,K) row-major)
// ---------------------------------------------------------------------------
__global__ void prep_w_kernel(const float* __restrict__ W,
                              const float* __restrict__ A,
                              const float* __restrict__ Bm) {
    __shared__ float sA[16 * 8];
    __shared__ float sB[1024 * 9];

    const int t = threadIdx.x;
    const int bo = blockIdx.x;       // 16 rows per block

    if (t < 128) sA[t] = A[(bo * 16 + (t >> 3)) * 8 + (t & 7)];

    for (int c = 0; c < 4; c++) {
        const int i0 = c * 1024;
        __syncthreads();
        for (int j = 0; j < 32; j++) {
            int li = t + j * 256;
            sB[(li >> 3) * 9 + (li & 7)] = Bm[i0 * 8 + li];
        }
        __syncthreads();
        for (int ol = 0; ol < 16; ol++) {
            const int o = bo * 16 + ol;
            float a0 = sA[ol * 8 + 0], a1 = sA[ol * 8 + 1];
            float a2 = sA[ol * 8 + 2], a3 = sA[ol * 8 + 3];
            float a4 = sA[ol * 8 + 4], a5 = sA[ol * 8 + 5];
            float a6 = sA[ol * 8 + 6], a7 = sA[ol * 8 + 7];
            for (int j = 0; j < 4; j++) {
                int il = t + j * 256;
                const float* br = &sB[il * 9];
                float d = a0 * br[0] + a1 * br[1] + a2 * br[2] + a3 * br[3]
                        + a4 * br[4] + a5 * br[5] + a6 * br[6] + a7 * br[7];
                int idx = o * KDIM + i0 + il;
                g_Wh[idx] = __float2half_rn(W[idx] + 2.0f * d);
            }
        }
    }
}

// ---------------------------------------------------------------------------
// Kernel 2: xh = fp16_rn(x)
// ---------------------------------------------------------------------------
__global__ void conv_x_kernel(const float4* __restrict__ x, int n8) {
    uint4* xh = reinterpret_cast<uint4*>(g_xh);
    for (int i = blockIdx.x * blockDim.x + threadIdx.x; i < n8;
         i += gridDim.x * blockDim.x) {
        float4 f0 = x[2 * i];
        float4 f1 = x[2 * i + 1];
        uint4 v;
        v.x = h2_bits(__floats2half2_rn(f0.x, f0.y));
        v.y = h2_bits(__floats2half2_rn(f0.z, f0.w));
        v.z = h2_bits(__floats2half2_rn(f1.x, f1.y));
        v.w = h2_bits(__floats2half2_rn(f1.z, f1.w));
        xh[i] = v;
    }
}

// ---------------------------------------------------------------------------
// Kernel 3: out = xh @ Wh^T + bias  (mma.sync f16 k16 + ldmatrix, 128x256)
// ---------------------------------------------------------------------------
__global__ __launch_bounds__(256, 1)
void lora_gemm_f16(const float* __restrict__ bias, float* __restrict__ out) {
    extern __shared__ float smem[];
    __shared__ float sbias[BN];

    const uint32_t sbase = smem_u32(smem);
    const int tid = threadIdx.x;
    const int wid = tid >> 5;
    const int lane = tid & 31;
    const int ntile = blockIdx.x;   // 0..15 (fastest: W' L2-resident)
    const int mtile = blockIdx.y;   // 0..63

    // warp tile 64x64: warp_m {0,1}, warp_n {0..3}
    const int mrow_s = (wid & 1) * 64;
    const int ncol_s = (wid >> 1) * 64;
    const int r0 = lane >> 2;       // 0..7  (epilogue row)
    const int c0 = lane & 3;        // 0..3  (epilogue col pair)

    sbias[tid] = bias[ntile * BN + tid];

    // ---- producer offsets ----
    const int prow = tid >> 3;           // 0..31
    const int pch  = tid & 7;            // 0..7
    const __half* Abase = g_xh + (size_t)(mtile * BM + prow) * KDIM + pch * 8;
    const __half* Bbase = g_Wh + (size_t)(ntile * BN + prow) * KDIM + pch * 8;
    uint32_t aswz[4], bswz[8];
    #pragma unroll
    for (int i = 0; i < 4; i++) aswz[i] = (uint32_t)swz_idx(prow + i * 32, pch * 4) * 4u;
    #pragma unroll
    for (int i = 0; i < 8; i++) bswz[i] = (uint32_t)swz_idx(prow + i * 32, pch * 4) * 4u;

    auto load_tile = [&](int kt, int s) {
        const uint32_t abytes = sbase + (uint32_t)(s * STAGE_W) * 4u;
        const uint32_t bbytes = abytes + A_TILE_W * 4u;
        const int kbase = kt * BKH;   // halves
        #pragma unroll
        for (int i = 0; i < 4; i++)            // A: 128 rows
            cp_async16(abytes + aswz[i], Abase + (size_t)(i * 32) * KDIM + kbase);
        #pragma unroll
        for (int i = 0; i < 8; i++)            // B: 256 rows
            cp_async16(bbytes + bswz[i], Bbase + (size_t)(i * 32) * KDIM + kbase);
        CP_COMMIT();
    };

    // ---- ldmatrix per-lane addressing ----
    // A (16x16 per mt): matrices 0..3 = (r0-7,k0-7),(r8-15,k0-7),(r0-7,k8-15),(r8-15,k8-15)
    //   lane -> matrix m = lane>>3;  rowoff = (m&1)*8;  chunkoff = (m>>1)
    // B (8x16 pair per np): matrices = (n0-7,k0-7),(n0-7,k8-15),(n8-15,k0-7),(n8-15,k8-15)
    //   lane -> matrix m = lane>>3;  rowoff = (m>>1)*8; chunkoff = (m&1)
    const int alr = lane & 7;
    const int a_c4 = (lane >> 4) & 1;              // A chunk offset 0/1
    const int b_c4 = (lane >> 3) & 1;              // B chunk offset 0/1
    uint32_t abase[4], bbase4[4];
    int arow7[4], brow7[4];
    #pragma unroll
    for (int mt = 0; mt < 4; mt++) {
        int row = mrow_s + mt * 16 + ((lane >> 3) & 1) * 8 + alr;
        abase[mt] = (uint32_t)row * 128u;
        arow7[mt] = row & 7;
    }
    #pragma unroll
    for (int np = 0; np < 4; np++) {
        int row = ncol_s + np * 16 + ((lane >> 4) & 1) * 8 + alr;
        bbase4[np] = (uint32_t)(A_TILE_W * 4) + (uint32_t)row * 128u;
        brow7[np] = row & 7;
    }

    #pragma unroll
    for (int s = 0; s < STAGES - 1; s++) load_tile(s, s);

    float acc[4][8][4];
    #pragma unroll
    for (int mt = 0; mt < 4; mt++)
        #pragma unroll
        for (int nt = 0; nt < 8; nt++)
            #pragma unroll
            for (int q = 0; q < 4; q++) acc[mt][nt][q] = 0.0f;

    for (int kt = 0; kt < KTILES; kt++) {
        const int s = kt & (STAGES - 1);
        if (kt <= KTILES - 3)       CP_WAIT(2);
        else if (kt == KTILES - 2)  CP_WAIT(1);
        else                        CP_WAIT(0);
        __syncthreads();

        const int nk = kt + STAGES - 1;
        if (nk < KTILES) load_tile(nk, nk & (STAGES - 1));

        const uint32_t stage_b = sbase + (uint32_t)(s * STAGE_W) * 4u;

        #pragma unroll
        for (int ks = 0; ks < 4; ks++) {       // 4 x k16 = BKH=64 halves
            const int ch = 2 * ks;             // 16B-chunk base for this k16
            uint32_t a[4][4], bfr[4][4];
            #pragma unroll
            for (int mt = 0; mt < 4; mt++)
                ldsm_x4(a[mt], stage_b + abase[mt]
                        + (uint32_t)((((ch + a_c4) ^ arow7[mt]) & 7) << 4));
            #pragma unroll
            for (int np = 0; np < 4; np++)
                ldsm_x4(bfr[np], stage_b + bbase4[np]
                        + (uint32_t)((((ch + b_c4) ^ brow7[np]) & 7) << 4));
            #pragma unroll
            for (int mt = 0; mt < 4; mt++)
                #pragma unroll
                for (int nt = 0; nt < 8; nt++)
                    mma_f16(acc[mt][nt], a[mt], &bfr[nt >> 1][(nt & 1) * 2]);
        }
    }

    // ---- epilogue: float2 stores with bias ----
    #pragma unroll
    for (int mt = 0; mt < 4; mt++) {
        const int m = mtile * BM + mrow_s + mt * 16 + r0;
        #pragma unroll
        for (int nt = 0; nt < 8; nt++) {
            const int nloc = ncol_s + nt * 8 + 2 * c0;
            const int n = ntile * BN + nloc;
            const float b0 = sbias[nloc], b1 = sbias[nloc + 1];
            float2 v0 = make_float2(acc[mt][nt][0] + b0, acc[mt][nt][1] + b1);
            float2 v1 = make_float2(acc[mt][nt][2] + b0, acc[mt][nt][3] + b1);
            *reinterpret_cast<float2*>(out + (size_t)m * NDIM + n) = v0;
            *reinterpret_cast<float2*>(out + (size_t)(m + 8) * NDIM + n) = v1;
        }
    }
}

// ---------------------------------------------------------------------------
extern "C" void kernel_launch(void* const* d_in, const int* in_sizes, int n_in,
                              void* d_out, int out_size) {
    const float* x = (const float*)d_in[0];   // (2,4096,4096)
    const float* W = (const float*)d_in[1];   // (4096,4096)
    const float* b = (const float*)d_in[2];   // (4096)
    const float* A = (const float*)d_in[3];   // (4096,8)
    const float* B = (const float*)d_in[4];   // (4096,8)
    float* out = (float*)d_out;

    cudaFuncSetAttribute(lora_gemm_f16,
                         cudaFuncAttributeMaxDynamicSharedMemorySize, SMEM_BYTES);

    prep_w_kernel<<<256, 256>>>(W, A, B);
    conv_x_kernel<<<2048, 256>>>(reinterpret_cast<const float4*>(x),
                                 (int)((size_t)MDIM * KDIM / 8));
    lora_gemm_f16<<<dim3(NDIM / BN, MDIM / BM), 256, SMEM_BYTES>>>(b, out);
}